// round 1
// baseline (speedup 1.0000x reference)
#include <cuda_runtime.h>

// ---------------------------------------------------------------------------
// VentralModel pooling: for each scale s, pooled[o,w] = sum_p m[o,p]*win[w,p]
// divided by count(win[w] > 1e-20). Plus mean luminance via win0 over image.
// Output layout: [s*1200 + o*300 + w] for s=0..3, then [4800 + w] luminance.
// ---------------------------------------------------------------------------

#define NW 300
#define ZT 1e-20f

// modulus scratch: s0 @0 (4*262144), s1 @1048576 (4*65536),
// s2 @1310720 (4*16384), s3 @1376256 (4*4096); total 1392640 floats (5.6 MB)
static __device__ float g_m[1392640];

__global__ __launch_bounds__(256) void modulus_kernel(
    const float* __restrict__ p0, const float* __restrict__ p1,
    const float* __restrict__ p2, const float* __restrict__ p3)
{
    int i = blockIdx.x * blockDim.x + threadIdx.x;   // grid covers 1392640 exactly
    const float2* p;
    int off;
    if (i < 1048576)      { p = (const float2*)p0; off = i; }
    else if (i < 1310720) { p = (const float2*)p1; off = i - 1048576; }
    else if (i < 1376256) { p = (const float2*)p2; off = i - 1310720; }
    else                  { p = (const float2*)p3; off = i - 1376256; }
    float2 v = p[off];
    g_m[i] = sqrtf(v.x * v.x + v.y * v.y);
}

static __device__ __forceinline__ float warp_red(float v) {
    #pragma unroll
    for (int o = 16; o > 0; o >>= 1)
        v += __shfl_down_sync(0xffffffffu, v, o);
    return v;
}

__global__ __launch_bounds__(256) void pool_kernel(
    const float* __restrict__ w0, const float* __restrict__ w1,
    const float* __restrict__ w2, const float* __restrict__ w3,
    const float* __restrict__ img, float* __restrict__ out)
{
    int task = blockIdx.x;            // 0..1199; scale 0 (heaviest) first
    int sc = task / NW;
    int w  = task % NW;

    const float* winp; const float* mp; int n;
    if (sc == 0)      { winp = w0; mp = g_m;           n = 262144; }
    else if (sc == 1) { winp = w1; mp = g_m + 1048576; n = 65536;  }
    else if (sc == 2) { winp = w2; mp = g_m + 1310720; n = 16384;  }
    else              { winp = w3; mp = g_m + 1376256; n = 4096;   }

    int nv = n >> 2;
    const float4* wv = (const float4*)winp + (size_t)w * nv;
    const float4* m0 = (const float4*)(mp);
    const float4* m1 = (const float4*)(mp + n);
    const float4* m2 = (const float4*)(mp + 2 * n);
    const float4* m3 = (const float4*)(mp + 3 * n);
    const float4* iv = (const float4*)img;

    float a0 = 0.f, a1 = 0.f, a2 = 0.f, a3 = 0.f, aL = 0.f, cf = 0.f;

    for (int i = threadIdx.x; i < nv; i += 256) {
        float4 q = wv[i];
        cf += (q.x > ZT ? 1.f : 0.f) + (q.y > ZT ? 1.f : 0.f)
            + (q.z > ZT ? 1.f : 0.f) + (q.w > ZT ? 1.f : 0.f);
        // Skip modulus/image loads entirely where the window is all-zero
        if (q.x != 0.f || q.y != 0.f || q.z != 0.f || q.w != 0.f) {
            float4 v;
            v = m0[i]; a0 += q.x*v.x + q.y*v.y + q.z*v.z + q.w*v.w;
            v = m1[i]; a1 += q.x*v.x + q.y*v.y + q.z*v.z + q.w*v.w;
            v = m2[i]; a2 += q.x*v.x + q.y*v.y + q.z*v.z + q.w*v.w;
            v = m3[i]; a3 += q.x*v.x + q.y*v.y + q.z*v.z + q.w*v.w;
            if (sc == 0) {            // fused mean-luminance: saves a 2nd win0 pass
                v = iv[i]; aL += q.x*v.x + q.y*v.y + q.z*v.z + q.w*v.w;
            }
        }
    }

    // block reduction of 6 accumulators
    __shared__ float sm[8][6];
    int lane = threadIdx.x & 31, wid = threadIdx.x >> 5;
    a0 = warp_red(a0); a1 = warp_red(a1); a2 = warp_red(a2);
    a3 = warp_red(a3); aL = warp_red(aL); cf = warp_red(cf);
    if (lane == 0) {
        sm[wid][0] = a0; sm[wid][1] = a1; sm[wid][2] = a2;
        sm[wid][3] = a3; sm[wid][4] = aL; sm[wid][5] = cf;
    }
    __syncthreads();
    if (threadIdx.x == 0) {
        float r0 = 0.f, r1 = 0.f, r2 = 0.f, r3 = 0.f, rL = 0.f, rc = 0.f;
        #pragma unroll
        for (int k = 0; k < 8; k++) {
            r0 += sm[k][0]; r1 += sm[k][1]; r2 += sm[k][2];
            r3 += sm[k][3]; rL += sm[k][4]; rc += sm[k][5];
        }
        float inv = 1.f / rc;
        int ob = sc * 1200;
        out[ob + 0 * NW + w] = r0 * inv;
        out[ob + 1 * NW + w] = r1 * inv;
        out[ob + 2 * NW + w] = r2 * inv;
        out[ob + 3 * NW + w] = r3 * inv;
        if (sc == 0) out[4800 + w] = rL * inv;
    }
}

extern "C" void kernel_launch(void* const* d_in, const int* in_sizes, int n_in,
                              void* d_out, int out_size)
{
    const float *img = nullptr, *p0 = nullptr, *p1 = nullptr, *p2 = nullptr, *p3 = nullptr;
    const float *w0 = nullptr, *w1 = nullptr, *w2 = nullptr, *w3 = nullptr;

    // identify inputs by element count (all distinct) — robust to ordering
    for (int i = 0; i < n_in; i++) {
        switch (in_sizes[i]) {
            case 262144:   img = (const float*)d_in[i]; break;   // image 512^2
            case 2097152:  p0  = (const float*)d_in[i]; break;   // pyr0 4*512^2*2
            case 78643200: w0  = (const float*)d_in[i]; break;   // win0 300*512^2
            case 524288:   p1  = (const float*)d_in[i]; break;   // pyr1
            case 19660800: w1  = (const float*)d_in[i]; break;   // win1
            case 131072:   p2  = (const float*)d_in[i]; break;   // pyr2
            case 4915200:  w2  = (const float*)d_in[i]; break;   // win2
            case 32768:    p3  = (const float*)d_in[i]; break;   // pyr3
            case 1228800:  w3  = (const float*)d_in[i]; break;   // win3
        }
    }

    modulus_kernel<<<5440, 256>>>(p0, p1, p2, p3);               // 1392640 / 256
    pool_kernel<<<1200, 256>>>(w0, w1, w2, w3, img, (float*)d_out);
}

// round 2
// speedup vs baseline: 2.5452x; 2.5452x over previous
#include <cuda_runtime.h>

// ---------------------------------------------------------------------------
// VentralModel pooling, round 2: chunked tasks + partial-sum scratch.
//   modulus_kernel : m = sqrt(re^2+im^2) for all scales -> g_m (5.6 MB, L2-res)
//   pool_kernel    : 1500 chunk-tasks, each 512 thr; partials -> g_part
//   finalize_kernel: combine chunks, divide by nonzero count, write out
// Output: [s*1200 + o*300 + w] s=0..3, then [4800 + w] mean luminance.
// ---------------------------------------------------------------------------

#define ZT 1e-20f

// modulus scratch: s0 @0 (4*262144), s1 @1048576 (4*65536),
// s2 @1310720 (4*16384), s3 @1376256 (4*4096)
static __device__ float g_m[1392640];
// per-task partials: [task*8 + {a0,a1,a2,a3,aL,cf}]
static __device__ float g_part[1500 * 8];

__global__ __launch_bounds__(256) void modulus_kernel(
    const float* __restrict__ p0, const float* __restrict__ p1,
    const float* __restrict__ p2, const float* __restrict__ p3)
{
    int i = blockIdx.x * blockDim.x + threadIdx.x;   // grid covers 1392640 exactly
    const float2* p;
    int off;
    if (i < 1048576)      { p = (const float2*)p0; off = i; }
    else if (i < 1310720) { p = (const float2*)p1; off = i - 1048576; }
    else if (i < 1376256) { p = (const float2*)p2; off = i - 1310720; }
    else                  { p = (const float2*)p3; off = i - 1376256; }
    float2 v = p[off];
    g_m[i] = sqrtf(v.x * v.x + v.y * v.y);
}

static __device__ __forceinline__ float warp_red(float v) {
    #pragma unroll
    for (int o = 16; o > 0; o >>= 1)
        v += __shfl_down_sync(0xffffffffu, v, o);
    return v;
}

// Task map (1500 blocks of 512 threads):
//  [0,600)     scale0: w = t>>1, half = t&1, chunk nv=32768 float4
//  [600,900)   scale1: nv=16384
//  [900,1200)  scale2: nv=4096
//  [1200,1500) scale3: nv=1024
__global__ __launch_bounds__(512) void pool_kernel(
    const float* __restrict__ w0, const float* __restrict__ w1,
    const float* __restrict__ w2, const float* __restrict__ w3,
    const float* __restrict__ img)
{
    int t = blockIdx.x;
    const float* winp; const float* mp;
    int n, nv_c, cw_off, m_off;
    bool do_img = false;

    if (t < 600) {
        int w = t >> 1, h = t & 1;
        winp = w0; mp = g_m; n = 262144;
        nv_c = 32768; cw_off = w * 65536 + h * 32768; m_off = h * 32768;
        do_img = true;
    } else if (t < 900) {
        int w = t - 600;
        winp = w1; mp = g_m + 1048576; n = 65536;
        nv_c = 16384; cw_off = w * 16384; m_off = 0;
    } else if (t < 1200) {
        int w = t - 900;
        winp = w2; mp = g_m + 1310720; n = 16384;
        nv_c = 4096; cw_off = w * 4096; m_off = 0;
    } else {
        int w = t - 1200;
        winp = w3; mp = g_m + 1376256; n = 4096;
        nv_c = 1024; cw_off = w * 1024; m_off = 0;
    }

    const float4* wv = (const float4*)winp + cw_off;
    const float4* m0 = (const float4*)mp + m_off;
    const float4* m1 = (const float4*)(mp + n) + m_off;
    const float4* m2 = (const float4*)(mp + 2 * n) + m_off;
    const float4* m3 = (const float4*)(mp + 3 * n) + m_off;
    const float4* iv = (const float4*)img + m_off;

    float a0 = 0.f, a1 = 0.f, a2 = 0.f, a3 = 0.f, aL = 0.f, cf = 0.f;

    // unroll x2: both window loads issued before any use -> high MLP;
    // __ldcs streams windows (read-once) so g_m/img stay L2-resident.
    for (int i = threadIdx.x; i < nv_c; i += 1024) {
        float4 q0 = __ldcs(wv + i);
        float4 q1 = __ldcs(wv + i + 512);

        cf += (q0.x > ZT ? 1.f : 0.f) + (q0.y > ZT ? 1.f : 0.f)
            + (q0.z > ZT ? 1.f : 0.f) + (q0.w > ZT ? 1.f : 0.f)
            + (q1.x > ZT ? 1.f : 0.f) + (q1.y > ZT ? 1.f : 0.f)
            + (q1.z > ZT ? 1.f : 0.f) + (q1.w > ZT ? 1.f : 0.f);

        if (q0.x != 0.f || q0.y != 0.f || q0.z != 0.f || q0.w != 0.f) {
            float4 v;
            v = m0[i]; a0 += q0.x*v.x + q0.y*v.y + q0.z*v.z + q0.w*v.w;
            v = m1[i]; a1 += q0.x*v.x + q0.y*v.y + q0.z*v.z + q0.w*v.w;
            v = m2[i]; a2 += q0.x*v.x + q0.y*v.y + q0.z*v.z + q0.w*v.w;
            v = m3[i]; a3 += q0.x*v.x + q0.y*v.y + q0.z*v.z + q0.w*v.w;
            if (do_img) { v = iv[i]; aL += q0.x*v.x + q0.y*v.y + q0.z*v.z + q0.w*v.w; }
        }
        if (q1.x != 0.f || q1.y != 0.f || q1.z != 0.f || q1.w != 0.f) {
            float4 v; int j = i + 512;
            v = m0[j]; a0 += q1.x*v.x + q1.y*v.y + q1.z*v.z + q1.w*v.w;
            v = m1[j]; a1 += q1.x*v.x + q1.y*v.y + q1.z*v.z + q1.w*v.w;
            v = m2[j]; a2 += q1.x*v.x + q1.y*v.y + q1.z*v.z + q1.w*v.w;
            v = m3[j]; a3 += q1.x*v.x + q1.y*v.y + q1.z*v.z + q1.w*v.w;
            if (do_img) { v = iv[j]; aL += q1.x*v.x + q1.y*v.y + q1.z*v.z + q1.w*v.w; }
        }
    }

    // block reduction (16 warps)
    __shared__ float sm[16][6];
    int lane = threadIdx.x & 31, wid = threadIdx.x >> 5;
    a0 = warp_red(a0); a1 = warp_red(a1); a2 = warp_red(a2);
    a3 = warp_red(a3); aL = warp_red(aL); cf = warp_red(cf);
    if (lane == 0) {
        sm[wid][0] = a0; sm[wid][1] = a1; sm[wid][2] = a2;
        sm[wid][3] = a3; sm[wid][4] = aL; sm[wid][5] = cf;
    }
    __syncthreads();
    if (threadIdx.x < 6) {
        float r = 0.f;
        #pragma unroll
        for (int k = 0; k < 16; k++) r += sm[k][threadIdx.x];
        g_part[t * 8 + threadIdx.x] = r;
    }
}

__global__ __launch_bounds__(256) void finalize_kernel(float* __restrict__ out)
{
    int tid = blockIdx.x * blockDim.x + threadIdx.x;
    if (tid >= 1200) return;
    int sc = tid / 300, w = tid % 300;
    float s0, s1, s2, s3, sL, sc_cnt;
    if (sc == 0) {
        const float* pa = g_part + (w * 2) * 8;
        const float* pb = g_part + (w * 2 + 1) * 8;
        s0 = pa[0] + pb[0]; s1 = pa[1] + pb[1]; s2 = pa[2] + pb[2];
        s3 = pa[3] + pb[3]; sL = pa[4] + pb[4]; sc_cnt = pa[5] + pb[5];
    } else {
        const float* p = g_part + (300 + sc * 300 + w) * 8;  // sc1->600+w, sc2->900+w, sc3->1200+w
        s0 = p[0]; s1 = p[1]; s2 = p[2]; s3 = p[3]; sL = p[4]; sc_cnt = p[5];
    }
    float inv = 1.f / sc_cnt;
    int ob = sc * 1200;
    out[ob + 0 * 300 + w] = s0 * inv;
    out[ob + 1 * 300 + w] = s1 * inv;
    out[ob + 2 * 300 + w] = s2 * inv;
    out[ob + 3 * 300 + w] = s3 * inv;
    if (sc == 0) out[4800 + w] = sL * inv;
}

extern "C" void kernel_launch(void* const* d_in, const int* in_sizes, int n_in,
                              void* d_out, int out_size)
{
    const float *img = nullptr, *p0 = nullptr, *p1 = nullptr, *p2 = nullptr, *p3 = nullptr;
    const float *w0 = nullptr, *w1 = nullptr, *w2 = nullptr, *w3 = nullptr;

    for (int i = 0; i < n_in; i++) {
        switch (in_sizes[i]) {
            case 262144:   img = (const float*)d_in[i]; break;   // image 512^2
            case 2097152:  p0  = (const float*)d_in[i]; break;   // pyr0
            case 78643200: w0  = (const float*)d_in[i]; break;   // win0
            case 524288:   p1  = (const float*)d_in[i]; break;   // pyr1
            case 19660800: w1  = (const float*)d_in[i]; break;   // win1
            case 131072:   p2  = (const float*)d_in[i]; break;   // pyr2
            case 4915200:  w2  = (const float*)d_in[i]; break;   // win2
            case 32768:    p3  = (const float*)d_in[i]; break;   // pyr3
            case 1228800:  w3  = (const float*)d_in[i]; break;   // win3
        }
    }

    modulus_kernel<<<5440, 256>>>(p0, p1, p2, p3);
    pool_kernel<<<1500, 512>>>(w0, w1, w2, w3, img);
    finalize_kernel<<<5, 256>>>((float*)d_out);
}

// round 3
// speedup vs baseline: 2.7348x; 1.0745x over previous
#include <cuda_runtime.h>

// ---------------------------------------------------------------------------
// VentralModel pooling, round 3: uniform chunking (s0 x4) + unroll x4 MLP.
//   modulus_kernel : m = sqrt(re^2+im^2), float4 path -> g_m (5.6 MB, L2-res)
//   pool_kernel    : 2100 chunk-tasks x 512 thr; partials -> g_part
//   finalize_kernel: combine chunks, divide by nonzero count, write out
// Output: [s*1200 + o*300 + w] s=0..3, then [4800 + w] mean luminance.
// ---------------------------------------------------------------------------

#define ZT 1e-20f

// modulus scratch: s0 @0 (4*262144), s1 @1048576 (4*65536),
// s2 @1310720 (4*16384), s3 @1376256 (4*4096)
static __device__ float g_m[1392640];
// per-task partials: [task*8 + {a0,a1,a2,a3,aL,cf}]
static __device__ float g_part[2100 * 8];

// Each thread: one float4 = 2 complex values -> 2 moduli (float2 store).
__global__ __launch_bounds__(256) void modulus_kernel(
    const float* __restrict__ p0, const float* __restrict__ p1,
    const float* __restrict__ p2, const float* __restrict__ p3)
{
    int i = blockIdx.x * blockDim.x + threadIdx.x;   // 696320 threads total
    int pi = i * 2;                                  // pair (modulus) index
    const float4* p;
    int off;
    if (pi < 1048576)      { p = (const float4*)p0; off = i; }
    else if (pi < 1310720) { p = (const float4*)p1; off = i - (1048576 >> 1); }
    else if (pi < 1376256) { p = (const float4*)p2; off = i - (1310720 >> 1); }
    else                   { p = (const float4*)p3; off = i - (1376256 >> 1); }
    float4 v = p[off];
    float2 r;
    r.x = sqrtf(v.x * v.x + v.y * v.y);
    r.y = sqrtf(v.z * v.z + v.w * v.w);
    *(float2*)(g_m + pi) = r;
}

static __device__ __forceinline__ float warp_red(float v) {
    #pragma unroll
    for (int o = 16; o > 0; o >>= 1)
        v += __shfl_down_sync(0xffffffffu, v, o);
    return v;
}

#define GROUP(Q, IDX)                                                          \
    do {                                                                       \
        float4 q_ = (Q); int i_ = (IDX);                                       \
        cf += (q_.x > ZT ? 1.f : 0.f) + (q_.y > ZT ? 1.f : 0.f)                \
            + (q_.z > ZT ? 1.f : 0.f) + (q_.w > ZT ? 1.f : 0.f);               \
        if (q_.x != 0.f || q_.y != 0.f || q_.z != 0.f || q_.w != 0.f) {        \
            float4 v_;                                                         \
            v_ = m0[i_]; a0 += q_.x*v_.x + q_.y*v_.y + q_.z*v_.z + q_.w*v_.w;  \
            v_ = m1[i_]; a1 += q_.x*v_.x + q_.y*v_.y + q_.z*v_.z + q_.w*v_.w;  \
            v_ = m2[i_]; a2 += q_.x*v_.x + q_.y*v_.y + q_.z*v_.z + q_.w*v_.w;  \
            v_ = m3[i_]; a3 += q_.x*v_.x + q_.y*v_.y + q_.z*v_.z + q_.w*v_.w;  \
            if (do_img) {                                                      \
                v_ = iv[i_]; aL += q_.x*v_.x + q_.y*v_.y + q_.z*v_.z + q_.w*v_.w; \
            }                                                                  \
        }                                                                      \
    } while (0)

// Task map (2100 blocks of 512 threads):
//  [0,1200)    scale0: w=t>>2, q=t&3, nv=16384 float4 (256 KB)
//  [1200,1500) scale1: nv=16384 (256 KB)
//  [1500,1800) scale2: nv=4096  (64 KB)
//  [1800,2100) scale3: nv=1024  (16 KB)
__global__ __launch_bounds__(512) void pool_kernel(
    const float* __restrict__ w0, const float* __restrict__ w1,
    const float* __restrict__ w2, const float* __restrict__ w3,
    const float* __restrict__ img)
{
    int t = blockIdx.x;
    const float* winp; const float* mp;
    int n, nv_c, cw_off, m_off;
    bool do_img = false;

    if (t < 1200) {
        int w = t >> 2, q = t & 3;
        winp = w0; mp = g_m; n = 262144;
        nv_c = 16384; cw_off = w * 65536 + q * 16384; m_off = q * 16384;
        do_img = true;
    } else if (t < 1500) {
        int w = t - 1200;
        winp = w1; mp = g_m + 1048576; n = 65536;
        nv_c = 16384; cw_off = w * 16384; m_off = 0;
    } else if (t < 1800) {
        int w = t - 1500;
        winp = w2; mp = g_m + 1310720; n = 16384;
        nv_c = 4096; cw_off = w * 4096; m_off = 0;
    } else {
        int w = t - 1800;
        winp = w3; mp = g_m + 1376256; n = 4096;
        nv_c = 1024; cw_off = w * 1024; m_off = 0;
    }

    const float4* wv = (const float4*)winp + cw_off;
    const float4* m0 = (const float4*)mp + m_off;
    const float4* m1 = (const float4*)(mp + n) + m_off;
    const float4* m2 = (const float4*)(mp + 2 * n) + m_off;
    const float4* m3 = (const float4*)(mp + 3 * n) + m_off;
    const float4* iv = (const float4*)img + m_off;

    float a0 = 0.f, a1 = 0.f, a2 = 0.f, a3 = 0.f, aL = 0.f, cf = 0.f;

    if (nv_c >= 2048) {
        // unroll x4, no guards (nv_c % 2048 == 0): 4 window loads in flight
        for (int i = threadIdx.x; i < nv_c; i += 2048) {
            float4 q0 = __ldcs(wv + i);
            float4 q1 = __ldcs(wv + i + 512);
            float4 q2 = __ldcs(wv + i + 1024);
            float4 q3 = __ldcs(wv + i + 1536);
            GROUP(q0, i);
            GROUP(q1, i + 512);
            GROUP(q2, i + 1024);
            GROUP(q3, i + 1536);
        }
    } else {
        for (int i = threadIdx.x; i < nv_c; i += 512) {
            float4 q0 = __ldcs(wv + i);
            GROUP(q0, i);
        }
    }

    // block reduction (16 warps)
    __shared__ float sm[16][6];
    int lane = threadIdx.x & 31, wid = threadIdx.x >> 5;
    a0 = warp_red(a0); a1 = warp_red(a1); a2 = warp_red(a2);
    a3 = warp_red(a3); aL = warp_red(aL); cf = warp_red(cf);
    if (lane == 0) {
        sm[wid][0] = a0; sm[wid][1] = a1; sm[wid][2] = a2;
        sm[wid][3] = a3; sm[wid][4] = aL; sm[wid][5] = cf;
    }
    __syncthreads();
    if (threadIdx.x < 6) {
        float r = 0.f;
        #pragma unroll
        for (int k = 0; k < 16; k++) r += sm[k][threadIdx.x];
        g_part[t * 8 + threadIdx.x] = r;
    }
}

__global__ __launch_bounds__(256) void finalize_kernel(float* __restrict__ out)
{
    int tid = blockIdx.x * blockDim.x + threadIdx.x;
    if (tid >= 1200) return;
    int sc = tid / 300, w = tid % 300;
    float s0 = 0.f, s1 = 0.f, s2 = 0.f, s3 = 0.f, sL = 0.f, cnt = 0.f;
    if (sc == 0) {
        #pragma unroll
        for (int q = 0; q < 4; q++) {
            const float* p = g_part + (w * 4 + q) * 8;
            s0 += p[0]; s1 += p[1]; s2 += p[2];
            s3 += p[3]; sL += p[4]; cnt += p[5];
        }
    } else {
        const float* p = g_part + (900 + sc * 300 + w) * 8;  // sc1->1200+w, sc2->1500+w, sc3->1800+w
        s0 = p[0]; s1 = p[1]; s2 = p[2]; s3 = p[3]; sL = p[4]; cnt = p[5];
    }
    float inv = 1.f / cnt;
    int ob = sc * 1200;
    out[ob + 0 * 300 + w] = s0 * inv;
    out[ob + 1 * 300 + w] = s1 * inv;
    out[ob + 2 * 300 + w] = s2 * inv;
    out[ob + 3 * 300 + w] = s3 * inv;
    if (sc == 0) out[4800 + w] = sL * inv;
}

extern "C" void kernel_launch(void* const* d_in, const int* in_sizes, int n_in,
                              void* d_out, int out_size)
{
    const float *img = nullptr, *p0 = nullptr, *p1 = nullptr, *p2 = nullptr, *p3 = nullptr;
    const float *w0 = nullptr, *w1 = nullptr, *w2 = nullptr, *w3 = nullptr;

    for (int i = 0; i < n_in; i++) {
        switch (in_sizes[i]) {
            case 262144:   img = (const float*)d_in[i]; break;   // image 512^2
            case 2097152:  p0  = (const float*)d_in[i]; break;   // pyr0
            case 78643200: w0  = (const float*)d_in[i]; break;   // win0
            case 524288:   p1  = (const float*)d_in[i]; break;   // pyr1
            case 19660800: w1  = (const float*)d_in[i]; break;   // win1
            case 131072:   p2  = (const float*)d_in[i]; break;   // pyr2
            case 4915200:  w2  = (const float*)d_in[i]; break;   // win2
            case 32768:    p3  = (const float*)d_in[i]; break;   // pyr3
            case 1228800:  w3  = (const float*)d_in[i]; break;   // win3
        }
    }

    modulus_kernel<<<2720, 256>>>(p0, p1, p2, p3);   // 696320 float4 threads
    pool_kernel<<<2100, 512>>>(w0, w1, w2, w3, img);
    finalize_kernel<<<5, 256>>>((float*)d_out);
}